// round 1
// baseline (speedup 1.0000x reference)
#include <cuda_runtime.h>
#include <cuda_bf16.h>
#include <mma.h>
#include <math.h>

using namespace nvcuda;

// ---------------- problem constants ----------------
#define T_TOK   4096
#define HDIM    3584
#define NH      28
#define NKV     4
#define DHEAD   128
#define GROUP   7
#define BATCH   4
#define SEQ     1024
#define QKV_N   4608              // (28 + 8) * 128
#define KCOL0   3584              // NH*D
#define VCOL0   4096              // (NH+NKV)*D
#define CACHE_HALF 4194304        // 8192 slots * 4 kv * 128
#define OUT_ELEMS ((size_t)T_TOK * HDIM)

__device__ float g_qkv[(size_t)T_TOK * QKV_N];   // qkv projection scratch (rope applied in place)
__device__ float g_ctx[(size_t)T_TOK * HDIM];    // attention output scratch

// ---------------- zero fill ----------------
__global__ void zero_kernel(float4* __restrict__ p, int n4) {
    int i = blockIdx.x * blockDim.x + threadIdx.x;
    int stride = gridDim.x * blockDim.x;
    float4 z = make_float4(0.f, 0.f, 0.f, 0.f);
    for (; i < n4; i += stride) p[i] = z;
}

// ---------------- TF32 GEMM: C[M,N] = A[M,K] * B[N,K]^T ----------------
#define BM 128
#define BN 128
#define BK 32
#define PADG 4

__global__ __launch_bounds__(256) void gemm_tf32_nt(
    const float* __restrict__ A, const float* __restrict__ B, float* __restrict__ C,
    int M, int N, int K)
{
    __shared__ float sA[BM][BK + PADG];
    __shared__ float sB[BN][BK + PADG];

    const int bm = blockIdx.y, bn = blockIdx.x;
    const int tid = threadIdx.x;
    const int warp = tid >> 5;
    const int wm = warp >> 2;   // 0..1 -> 64 rows each
    const int wn = warp & 3;    // 0..3 -> 32 cols each

    wmma::fragment<wmma::accumulator, 16, 16, 8, float> cfr[4][2];
#pragma unroll
    for (int i = 0; i < 4; i++)
#pragma unroll
        for (int j = 0; j < 2; j++) wmma::fill_fragment(cfr[i][j], 0.f);

    const float* Ab = A + (size_t)bm * BM * K;
    const float* Bb = B + (size_t)bn * BN * K;

    for (int k0 = 0; k0 < K; k0 += BK) {
#pragma unroll
        for (int i = 0; i < 4; i++) {
            int idx = i * 256 + tid;
            int r = idx >> 3, c4 = (idx & 7) << 2;
            float4 v = *reinterpret_cast<const float4*>(Ab + (size_t)r * K + k0 + c4);
            v.x = wmma::__float_to_tf32(v.x); v.y = wmma::__float_to_tf32(v.y);
            v.z = wmma::__float_to_tf32(v.z); v.w = wmma::__float_to_tf32(v.w);
            *reinterpret_cast<float4*>(&sA[r][c4]) = v;
        }
#pragma unroll
        for (int i = 0; i < 4; i++) {
            int idx = i * 256 + tid;
            int r = idx >> 3, c4 = (idx & 7) << 2;
            float4 v = *reinterpret_cast<const float4*>(Bb + (size_t)r * K + k0 + c4);
            v.x = wmma::__float_to_tf32(v.x); v.y = wmma::__float_to_tf32(v.y);
            v.z = wmma::__float_to_tf32(v.z); v.w = wmma::__float_to_tf32(v.w);
            *reinterpret_cast<float4*>(&sB[r][c4]) = v;
        }
        __syncthreads();

#pragma unroll
        for (int kk = 0; kk < BK / 8; kk++) {
            wmma::fragment<wmma::matrix_a, 16, 16, 8, wmma::precision::tf32, wmma::row_major> af[4];
            wmma::fragment<wmma::matrix_b, 16, 16, 8, wmma::precision::tf32, wmma::col_major> bf[2];
#pragma unroll
            for (int i = 0; i < 4; i++)
                wmma::load_matrix_sync(af[i], &sA[wm * 64 + i * 16][kk * 8], BK + PADG);
#pragma unroll
            for (int j = 0; j < 2; j++)
                wmma::load_matrix_sync(bf[j], &sB[wn * 32 + j * 16][kk * 8], BK + PADG);
#pragma unroll
            for (int i = 0; i < 4; i++)
#pragma unroll
                for (int j = 0; j < 2; j++)
                    wmma::mma_sync(cfr[i][j], af[i], bf[j], cfr[i][j]);
        }
        __syncthreads();
    }

#pragma unroll
    for (int i = 0; i < 4; i++)
#pragma unroll
        for (int j = 0; j < 2; j++) {
            size_t row = (size_t)bm * BM + wm * 64 + i * 16;
            size_t col = (size_t)bn * BN + wn * 32 + j * 16;
            wmma::store_matrix_sync(C + row * N + col, cfr[i][j], N, wmma::mem_row_major);
        }
}

// ---------------- bias + RoPE + cache scatter ----------------
__global__ __launch_bounds__(64) void epi_kernel(
    float* __restrict__ qkv, const float* __restrict__ bias,
    const int* __restrict__ positions, const int* __restrict__ slot_mapping,
    float* __restrict__ cache)
{
    int t = blockIdx.x;
    int d = threadIdx.x;          // 0..63, handles pair (d, d+64)
    float p = (float)positions[t];
    // inv_freq = 10000^(-d/64), computed in double for <=1ulp agreement
    float inv = (float)exp2(-(double)d * (13.287712379549449 / 64.0));
    float ang = p * inv;
    float s, c;
    sincosf(ang, &s, &c);
    int slot = slot_mapping[t];
    float* row = qkv + (size_t)t * QKV_N;
    float* kc = cache + (size_t)slot * (NKV * DHEAD);
    float* vc = cache + CACHE_HALF + (size_t)slot * (NKV * DHEAD);

#pragma unroll
    for (int h = 0; h < NH; h++) {
        int base = h * DHEAD;
        float x1 = row[base + d]      + bias[base + d];
        float x2 = row[base + d + 64] + bias[base + d + 64];
        row[base + d]      = x1 * c - x2 * s;
        row[base + d + 64] = x2 * c + x1 * s;
    }
#pragma unroll
    for (int hk = 0; hk < NKV; hk++) {
        int base = KCOL0 + hk * DHEAD;
        float x1 = row[base + d]      + bias[base + d];
        float x2 = row[base + d + 64] + bias[base + d + 64];
        float y1 = x1 * c - x2 * s;
        float y2 = x2 * c + x1 * s;
        row[base + d] = y1; row[base + d + 64] = y2;
        kc[hk * DHEAD + d] = y1; kc[hk * DHEAD + d + 64] = y2;
    }
#pragma unroll
    for (int hv = 0; hv < NKV; hv++) {
        int base = VCOL0 + hv * DHEAD;
        float x1 = row[base + d]      + bias[base + d];
        float x2 = row[base + d + 64] + bias[base + d + 64];
        row[base + d] = x1; row[base + d + 64] = x2;
        vc[hv * DHEAD + d] = x1; vc[hv * DHEAD + d + 64] = x2;
    }
}

// ---------------- flash attention (TF32 wmma) ----------------
#define APAD 4
#define QLD  (DHEAD + APAD)     // 132
#define SLD  (64 + APAD)        // 68
#define ATTN_SMEM_FLOATS (4 * 64 * QLD + 64 * SLD + 3 * 64)
#define ATTN_SMEM_BYTES  (ATTN_SMEM_FLOATS * 4)

__global__ __launch_bounds__(256) void attn_kernel(
    const float* __restrict__ qkv, float* __restrict__ ctx)
{
    extern __shared__ float sm[];
    float* Qs = sm;                       // 64 x 132
    float* Ks = Qs + 64 * QLD;            // 64 x 132
    float* Vs = Ks + 64 * QLD;            // 64 x 132
    float* Os = Vs + 64 * QLD;            // 64 x 132
    float* Ss = Os + 64 * QLD;            // 64 x 68
    float* rm = Ss + 64 * SLD;            // 64
    float* rl = rm + 64;                  // 64
    float* ra = rl + 64;                  // 64

    const int qt = blockIdx.x;            // q tile (16)
    const int h  = blockIdx.y;            // head (28)
    const int b  = blockIdx.z;            // batch (4)
    const int tid = threadIdx.x;
    const int warp = tid >> 5, lane = tid & 31;
    const int kv = h / GROUP;
    const int t0 = b * SEQ + qt * 64;
    const int qcol = h * DHEAD;
    const int kcol = KCOL0 + kv * DHEAD;
    const int vcol = VCOL0 + kv * DHEAD;
    const float SCALE = 0.08838834764831845f;

    // load Q tile, zero O
#pragma unroll
    for (int i = 0; i < 8; i++) {
        int idx = i * 256 + tid;
        int r = idx >> 5, c4 = (idx & 31) << 2;
        float4 v = *reinterpret_cast<const float4*>(&qkv[(size_t)(t0 + r) * QKV_N + qcol + c4]);
        v.x = wmma::__float_to_tf32(v.x); v.y = wmma::__float_to_tf32(v.y);
        v.z = wmma::__float_to_tf32(v.z); v.w = wmma::__float_to_tf32(v.w);
        *reinterpret_cast<float4*>(&Qs[r * QLD + c4]) = v;
        *reinterpret_cast<float4*>(&Os[r * QLD + c4]) = make_float4(0.f, 0.f, 0.f, 0.f);
    }
    if (tid < 64) { rm[tid] = -1e30f; rl[tid] = 0.f; }
    __syncthreads();

    for (int kt = 0; kt <= qt; kt++) {
        const int s0 = b * SEQ + kt * 64;
#pragma unroll
        for (int i = 0; i < 8; i++) {
            int idx = i * 256 + tid;
            int r = idx >> 5, c4 = (idx & 31) << 2;
            float4 kvec = *reinterpret_cast<const float4*>(&qkv[(size_t)(s0 + r) * QKV_N + kcol + c4]);
            kvec.x = wmma::__float_to_tf32(kvec.x); kvec.y = wmma::__float_to_tf32(kvec.y);
            kvec.z = wmma::__float_to_tf32(kvec.z); kvec.w = wmma::__float_to_tf32(kvec.w);
            *reinterpret_cast<float4*>(&Ks[r * QLD + c4]) = kvec;
            float4 vvec = *reinterpret_cast<const float4*>(&qkv[(size_t)(s0 + r) * QKV_N + vcol + c4]);
            vvec.x = wmma::__float_to_tf32(vvec.x); vvec.y = wmma::__float_to_tf32(vvec.y);
            vvec.z = wmma::__float_to_tf32(vvec.z); vvec.w = wmma::__float_to_tf32(vvec.w);
            *reinterpret_cast<float4*>(&Vs[r * QLD + c4]) = vvec;
        }
        __syncthreads();

        // S = Q K^T * SCALE  (64x64, 16 tiles of 16x16, 2 per warp)
#pragma unroll
        for (int tt = 0; tt < 2; tt++) {
            int tile = warp + tt * 8;
            int tm = tile >> 2, tn = tile & 3;
            wmma::fragment<wmma::accumulator, 16, 16, 8, float> sc;
            wmma::fill_fragment(sc, 0.f);
#pragma unroll
            for (int ks = 0; ks < 16; ks++) {
                wmma::fragment<wmma::matrix_a, 16, 16, 8, wmma::precision::tf32, wmma::row_major> af;
                wmma::fragment<wmma::matrix_b, 16, 16, 8, wmma::precision::tf32, wmma::col_major> bf;
                wmma::load_matrix_sync(af, &Qs[tm * 16 * QLD + ks * 8], QLD);
                wmma::load_matrix_sync(bf, &Ks[tn * 16 * QLD + ks * 8], QLD);
                wmma::mma_sync(sc, af, bf, sc);
            }
#pragma unroll
            for (int e = 0; e < sc.num_elements; e++) sc.x[e] *= SCALE;
            wmma::store_matrix_sync(&Ss[tm * 16 * SLD + tn * 16], sc, SLD, wmma::mem_row_major);
        }
        __syncthreads();

        // online softmax: warp handles 8 rows
        const bool diag = (kt == qt);
#pragma unroll
        for (int rr = 0; rr < 8; rr++) {
            int r = warp * 8 + rr;
            float v0 = Ss[r * SLD + lane];
            float v1 = Ss[r * SLD + lane + 32];
            if (diag) {
                if (lane > r) v0 = -1e30f;
                if (lane + 32 > r) v1 = -1e30f;
            }
            float mx = fmaxf(v0, v1);
#pragma unroll
            for (int o = 16; o; o >>= 1) mx = fmaxf(mx, __shfl_xor_sync(0xffffffffu, mx, o));
            float m_old = rm[r];
            float m_new = fmaxf(m_old, mx);
            float p0 = __expf(v0 - m_new);
            float p1 = __expf(v1 - m_new);
            Ss[r * SLD + lane] = p0;
            Ss[r * SLD + lane + 32] = p1;
            float su = p0 + p1;
#pragma unroll
            for (int o = 16; o; o >>= 1) su += __shfl_xor_sync(0xffffffffu, su, o);
            if (lane == 0) {
                float alpha = __expf(m_old - m_new);
                ra[r] = alpha;
                rl[r] = rl[r] * alpha + su;
                rm[r] = m_new;
            }
        }
        __syncthreads();

        // rescale O
#pragma unroll
        for (int i = 0; i < 8; i++) {
            int idx = i * 256 + tid;
            int r = idx >> 5, c4 = (idx & 31) << 2;
            float a = ra[r];
            float4* pp = reinterpret_cast<float4*>(&Os[r * QLD + c4]);
            float4 v = *pp;
            v.x *= a; v.y *= a; v.z *= a; v.w *= a;
            *pp = v;
        }
        __syncthreads();

        // O += P V   (64x128, warp handles 16x64 strip: tm = warp>>1, tn in 4)
        {
            int tm = warp >> 1;
            int tnb = (warp & 1) * 4;
            wmma::fragment<wmma::matrix_a, 16, 16, 8, wmma::precision::tf32, wmma::row_major> af[8];
#pragma unroll
            for (int ks = 0; ks < 8; ks++) {
                wmma::load_matrix_sync(af[ks], &Ss[tm * 16 * SLD + ks * 8], SLD);
#pragma unroll
                for (int e = 0; e < af[ks].num_elements; e++)
                    af[ks].x[e] = wmma::__float_to_tf32(af[ks].x[e]);
            }
#pragma unroll
            for (int j = 0; j < 4; j++) {
                int tn = tnb + j;
                wmma::fragment<wmma::accumulator, 16, 16, 8, float> of;
                wmma::load_matrix_sync(of, &Os[tm * 16 * QLD + tn * 16], QLD, wmma::mem_row_major);
#pragma unroll
                for (int ks = 0; ks < 8; ks++) {
                    wmma::fragment<wmma::matrix_b, 16, 16, 8, wmma::precision::tf32, wmma::row_major> bf;
                    wmma::load_matrix_sync(bf, &Vs[ks * 8 * QLD + tn * 16], QLD);
                    wmma::mma_sync(of, af[ks], bf, of);
                }
                wmma::store_matrix_sync(&Os[tm * 16 * QLD + tn * 16], of, QLD, wmma::mem_row_major);
            }
        }
        __syncthreads();
    }

    // normalize + write ctx
#pragma unroll
    for (int i = 0; i < 8; i++) {
        int idx = i * 256 + tid;
        int r = idx >> 5, c4 = (idx & 31) << 2;
        float inv = 1.f / rl[r];
        float4 v = *reinterpret_cast<float4*>(&Os[r * QLD + c4]);
        v.x *= inv; v.y *= inv; v.z *= inv; v.w *= inv;
        *reinterpret_cast<float4*>(&ctx[(size_t)(t0 + r) * HDIM + h * DHEAD + c4]) = v;
    }
}

// ---------------- launch ----------------
extern "C" void kernel_launch(void* const* d_in, const int* in_sizes, int n_in,
                              void* d_out, int out_size)
{
    const int*   positions    = (const int*)d_in[0];
    const float* hidden       = (const float*)d_in[1];
    const int*   slot_mapping = (const int*)d_in[4];
    const float* w_qkv        = (const float*)d_in[n_in - 3];
    const float* b_qkv        = (const float*)d_in[n_in - 2];
    const float* w_o          = (const float*)d_in[n_in - 1];

    float* out   = (float*)d_out;
    float* cache = out + OUT_ELEMS;

    float* qkv = nullptr;
    float* ctx = nullptr;
    cudaGetSymbolAddress((void**)&qkv, g_qkv);
    cudaGetSymbolAddress((void**)&ctx, g_ctx);

    cudaFuncSetAttribute(attn_kernel, cudaFuncAttributeMaxDynamicSharedMemorySize, ATTN_SMEM_BYTES);

    // 1. zero cache region (2 * 8192 * 512 floats)
    zero_kernel<<<1024, 256>>>((float4*)cache, (2 * CACHE_HALF) / 4);

    // 2. qkv = hidden @ w_qkv^T
    gemm_tf32_nt<<<dim3(QKV_N / BN, T_TOK / BM), 256>>>(hidden, w_qkv, qkv, T_TOK, QKV_N, HDIM);

    // 3. bias + rope + cache scatter
    epi_kernel<<<T_TOK, 64>>>(qkv, b_qkv, positions, slot_mapping, cache);

    // 4. attention -> ctx
    attn_kernel<<<dim3(SEQ / 64, NH, BATCH), 256, ATTN_SMEM_BYTES>>>(qkv, ctx);

    // 5. out = ctx @ w_o^T
    gemm_tf32_nt<<<dim3(HDIM / BN, T_TOK / BM), 256>>>(ctx, w_o, out, T_TOK, HDIM, HDIM);
}

// round 4
// speedup vs baseline: 1.5257x; 1.5257x over previous
#include <cuda_runtime.h>
#include <cuda_bf16.h>
#include <mma.h>
#include <math.h>
#include <cstdint>

using namespace nvcuda;

// ---------------- problem constants ----------------
#define T_TOK   4096
#define HDIM    3584
#define NH      28
#define NKV     4
#define DHEAD   128
#define GROUP   7
#define BATCH   4
#define SEQ     1024
#define QKV_N   4608              // (28 + 8) * 128
#define KCOL0   3584              // NH*D
#define VCOL0   4096              // (NH+NKV)*D
#define CACHE_HALF 4194304        // 8192 slots * 4 kv * 128
#define OUT_ELEMS ((size_t)T_TOK * HDIM)

__device__ float g_qkv[(size_t)T_TOK * QKV_N];   // qkv projection scratch (rope applied in place)
__device__ float g_ctx[(size_t)T_TOK * HDIM];    // attention output scratch

// ---------------- zero fill ----------------
__global__ void zero_kernel(float4* __restrict__ p, int n4) {
    int i = blockIdx.x * blockDim.x + threadIdx.x;
    int stride = gridDim.x * blockDim.x;
    float4 z = make_float4(0.f, 0.f, 0.f, 0.f);
    for (; i < n4; i += stride) p[i] = z;
}

// ---------------- cp.async helpers ----------------
__device__ __forceinline__ void cp_async16(void* dst, const void* src) {
    unsigned s = (unsigned)__cvta_generic_to_shared(dst);
    asm volatile("cp.async.cg.shared.global [%0], [%1], 16;\n" :: "r"(s), "l"(src));
}
__device__ __forceinline__ void cp_commit() {
    asm volatile("cp.async.commit_group;\n");
}
__device__ __forceinline__ void cp_wait0() {
    asm volatile("cp.async.wait_group 0;\n" ::: "memory");
}

// RN tf32 rounding (cvt.rna.tf32.f32)
__device__ __forceinline__ float tf32rn(float x) { return wmma::__float_to_tf32(x); }

// ---------------- TF32 GEMM: C[M,N] = A[M,K] * B[N,K]^T (double buffered) ----------------
#define BM 128
#define BN 128
#define BK 32
#define LDT 40                     // smem row stride (floats)
#define GEMM_SMEM_BYTES (2 * (BM + BN) * LDT * 4)

__global__ __launch_bounds__(256) void gemm_tf32_nt(
    const float* __restrict__ A, const float* __restrict__ B, float* __restrict__ C,
    int M, int N, int K)
{
    extern __shared__ float smg[];
    float* sA = smg;                       // [2][BM*LDT]
    float* sB = smg + 2 * BM * LDT;        // [2][BN*LDT]

    const int bm = blockIdx.y, bn = blockIdx.x;
    const int tid = threadIdx.x;
    const int warp = tid >> 5;
    const int wm = warp >> 2;   // 0..1 -> 64 rows each
    const int wn = warp & 3;    // 0..3 -> 32 cols each

    const float* Ab = A + (size_t)bm * BM * K;
    const float* Bb = B + (size_t)bn * BN * K;

    wmma::fragment<wmma::accumulator, 16, 16, 8, float> cfr[4][2];
#pragma unroll
    for (int i = 0; i < 4; i++)
#pragma unroll
        for (int j = 0; j < 2; j++) wmma::fill_fragment(cfr[i][j], 0.f);

    auto load_tile = [&](int k0, int buf) {
#pragma unroll
        for (int i = 0; i < 4; i++) {
            int id = i * 256 + tid;
            int r = id >> 3, c = (id & 7) << 2;
            cp_async16(&sA[buf * BM * LDT + r * LDT + c], Ab + (size_t)r * K + k0 + c);
        }
#pragma unroll
        for (int i = 0; i < 4; i++) {
            int id = i * 256 + tid;
            int r = id >> 3, c = (id & 7) << 2;
            cp_async16(&sB[buf * BN * LDT + r * LDT + c], Bb + (size_t)r * K + k0 + c);
        }
    };

    int buf = 0;
    load_tile(0, 0);
    cp_commit();

    for (int k0 = 0; k0 < K; k0 += BK) {
        cp_wait0();
        __syncthreads();
        if (k0 + BK < K) { load_tile(k0 + BK, buf ^ 1); cp_commit(); }

        const float* cA = sA + buf * BM * LDT;
        const float* cB = sB + buf * BN * LDT;
#pragma unroll
        for (int kk = 0; kk < BK / 8; kk++) {
            wmma::fragment<wmma::matrix_a, 16, 16, 8, wmma::precision::tf32, wmma::row_major> af[4];
            wmma::fragment<wmma::matrix_b, 16, 16, 8, wmma::precision::tf32, wmma::col_major> bf[2];
#pragma unroll
            for (int i = 0; i < 4; i++) {
                wmma::load_matrix_sync(af[i], &cA[(wm * 64 + i * 16) * LDT + kk * 8], LDT);
#pragma unroll
                for (int e = 0; e < af[i].num_elements; e++) af[i].x[e] = tf32rn(af[i].x[e]);
            }
#pragma unroll
            for (int j = 0; j < 2; j++) {
                wmma::load_matrix_sync(bf[j], &cB[(wn * 32 + j * 16) * LDT + kk * 8], LDT);
#pragma unroll
                for (int e = 0; e < bf[j].num_elements; e++) bf[j].x[e] = tf32rn(bf[j].x[e]);
            }
#pragma unroll
            for (int i = 0; i < 4; i++)
#pragma unroll
                for (int j = 0; j < 2; j++)
                    wmma::mma_sync(cfr[i][j], af[i], bf[j], cfr[i][j]);
        }
        __syncthreads();
        buf ^= 1;
    }

#pragma unroll
    for (int i = 0; i < 4; i++)
#pragma unroll
        for (int j = 0; j < 2; j++) {
            size_t row = (size_t)bm * BM + wm * 64 + i * 16;
            size_t col = (size_t)bn * BN + wn * 32 + j * 16;
            wmma::store_matrix_sync(C + row * N + col, cfr[i][j], N, wmma::mem_row_major);
        }
}

// ---------------- bias + RoPE + cache scatter ----------------
__global__ __launch_bounds__(64) void epi_kernel(
    float* __restrict__ qkv, const float* __restrict__ bias,
    const int* __restrict__ positions, const int* __restrict__ slot_mapping,
    float* __restrict__ cache)
{
    int t = blockIdx.x;
    int d = threadIdx.x;          // 0..63, handles pair (d, d+64)
    float p = (float)positions[t];
    float inv = (float)exp2(-(double)d * (13.287712379549449 / 64.0));
    float ang = p * inv;
    float s, c;
    sincosf(ang, &s, &c);
    int slot = slot_mapping[t];
    float* row = qkv + (size_t)t * QKV_N;
    float* kc = cache + (size_t)slot * (NKV * DHEAD);
    float* vc = cache + CACHE_HALF + (size_t)slot * (NKV * DHEAD);

#pragma unroll
    for (int h = 0; h < NH; h++) {
        int base = h * DHEAD;
        float x1 = row[base + d]      + bias[base + d];
        float x2 = row[base + d + 64] + bias[base + d + 64];
        row[base + d]      = x1 * c - x2 * s;
        row[base + d + 64] = x2 * c + x1 * s;
    }
#pragma unroll
    for (int hk = 0; hk < NKV; hk++) {
        int base = KCOL0 + hk * DHEAD;
        float x1 = row[base + d]      + bias[base + d];
        float x2 = row[base + d + 64] + bias[base + d + 64];
        float y1 = x1 * c - x2 * s;
        float y2 = x2 * c + x1 * s;
        row[base + d] = y1; row[base + d + 64] = y2;
        kc[hk * DHEAD + d] = y1; kc[hk * DHEAD + d + 64] = y2;
    }
#pragma unroll
    for (int hv = 0; hv < NKV; hv++) {
        int base = VCOL0 + hv * DHEAD;
        float x1 = row[base + d]      + bias[base + d];
        float x2 = row[base + d + 64] + bias[base + d + 64];
        row[base + d] = x1; row[base + d + 64] = x2;
        vc[hv * DHEAD + d] = x1; vc[hv * DHEAD + d + 64] = x2;
    }
}

// ---------------- flash attention v2: mma.sync tf32, register O ----------------
#define QT   128                  // q tile rows
#define KT   64                   // k tile rows
#define QLD  132                  // Qs/Ks stride (floats)
#define VLD  136                  // Vs stride (floats) - conflict-free PV B loads
#define SLD  68                   // P strip stride
// smem: Q 128x132, K 64x132, V 64x136, S 128x68
#define ATTN_SMEM_FLOATS (QT * QLD + KT * QLD + KT * VLD + QT * SLD)
#define ATTN_SMEM_BYTES  (ATTN_SMEM_FLOATS * 4)

__device__ __forceinline__ void mma8(float c[4],
    unsigned a0, unsigned a1, unsigned a2, unsigned a3, unsigned b0, unsigned b1)
{
    asm volatile(
        "mma.sync.aligned.m16n8k8.row.col.f32.tf32.tf32.f32 "
        "{%0,%1,%2,%3}, {%4,%5,%6,%7}, {%8,%9}, {%0,%1,%2,%3};\n"
        : "+f"(c[0]), "+f"(c[1]), "+f"(c[2]), "+f"(c[3])
        : "r"(a0), "r"(a1), "r"(a2), "r"(a3), "r"(b0), "r"(b1));
}
__device__ __forceinline__ unsigned fbits(float x) { return __float_as_uint(x); }

__global__ __launch_bounds__(256) void attn_kernel(
    const float* __restrict__ qkv, float* __restrict__ ctx)
{
    extern __shared__ float sm[];
    float* Qs = sm;                       // 128 x 132
    float* Ks = Qs + QT * QLD;            // 64 x 132
    float* Vs = Ks + KT * QLD;            // 64 x 136
    float* Ss = Vs + KT * VLD;            // 128 x 68 (P, warp-private strips)

    const int qt = blockIdx.x;            // q tile (8)
    const int h  = blockIdx.y;            // head (28)
    const int b  = blockIdx.z;            // batch (4)
    const int tid  = threadIdx.x;
    const int warp = tid >> 5, lane = tid & 31;
    const int g   = lane >> 2;            // group id (row within 8)
    const int tig = lane & 3;             // thread in group
    const int kv = h / GROUP;
    const int t0 = b * SEQ + qt * QT;
    const int qcol = h * DHEAD;
    const int kcol = KCOL0 + kv * DHEAD;
    const int vcol = VCOL0 + kv * DHEAD;
    const float SCALE = 0.08838834764831845f;

    // load Q tile (pre-scaled, RN tf32)
#pragma unroll
    for (int i = 0; i < 16; i++) {
        int idx = i * 256 + tid;
        int r = idx >> 5, c4 = (idx & 31) << 2;
        float4 v = *reinterpret_cast<const float4*>(&qkv[(size_t)(t0 + r) * QKV_N + qcol + c4]);
        v.x = tf32rn(v.x * SCALE); v.y = tf32rn(v.y * SCALE);
        v.z = tf32rn(v.z * SCALE); v.w = tf32rn(v.w * SCALE);
        *reinterpret_cast<float4*>(&Qs[r * QLD + c4]) = v;
    }

    float o[16][4];
#pragma unroll
    for (int i = 0; i < 16; i++) { o[i][0] = o[i][1] = o[i][2] = o[i][3] = 0.f; }
    float m0 = -1e30f, m1 = -1e30f, l0 = 0.f, l1 = 0.f;

    const float* Qw  = Qs + (warp * 16 + g) * QLD;
    const float* Qw8 = Qw + 8 * QLD;
    float* Pw  = Ss + (warp * 16 + g) * SLD;
    float* Pw8 = Pw + 8 * SLD;
    const int qr0 = qt * QT + warp * 16 + g;     // row position within sequence
    const int qr1 = qr0 + 8;

    const int ktmax = 2 * qt + 1;
    for (int kt = 0; kt <= ktmax; kt++) {
        const int s0 = b * SEQ + kt * KT;
        __syncthreads();   // prev PV done with Ks/Vs (& Q visible on first iter)
#pragma unroll
        for (int i = 0; i < 8; i++) {
            int idx = i * 256 + tid;
            int r = idx >> 5, c4 = (idx & 31) << 2;
            float4 kvec = *reinterpret_cast<const float4*>(&qkv[(size_t)(s0 + r) * QKV_N + kcol + c4]);
            kvec.x = tf32rn(kvec.x); kvec.y = tf32rn(kvec.y);
            kvec.z = tf32rn(kvec.z); kvec.w = tf32rn(kvec.w);
            *reinterpret_cast<float4*>(&Ks[r * QLD + c4]) = kvec;
            float4 vvec = *reinterpret_cast<const float4*>(&qkv[(size_t)(s0 + r) * QKV_N + vcol + c4]);
            vvec.x = tf32rn(vvec.x); vvec.y = tf32rn(vvec.y);
            vvec.z = tf32rn(vvec.z); vvec.w = tf32rn(vvec.w);
            *reinterpret_cast<float4*>(&Vs[r * VLD + c4]) = vvec;
        }
        __syncthreads();

        // ---- S = Q K^T (strip 16 x 64 per warp, in regs) ----
        float s[8][4];
#pragma unroll
        for (int nt = 0; nt < 8; nt++) { s[nt][0] = s[nt][1] = s[nt][2] = s[nt][3] = 0.f; }
#pragma unroll
        for (int ks = 0; ks < 16; ks++) {
            int kc = ks * 8 + tig;
            unsigned a0 = fbits(Qw[kc]);
            unsigned a1 = fbits(Qw8[kc]);
            unsigned a2 = fbits(Qw[kc + 4]);
            unsigned a3 = fbits(Qw8[kc + 4]);
#pragma unroll
            for (int nt = 0; nt < 8; nt++) {
                const float* Kr = Ks + (nt * 8 + g) * QLD;
                unsigned b0 = fbits(Kr[ks * 8 + tig]);
                unsigned b1 = fbits(Kr[ks * 8 + tig + 4]);
                mma8(s[nt], a0, a1, a2, a3, b0, b1);
            }
        }

        // ---- causal mask (only last two k-tiles can cross the diagonal) ----
        if (kt >= 2 * qt) {
            int colb = kt * KT + 2 * tig;
#pragma unroll
            for (int nt = 0; nt < 8; nt++) {
                int c0 = colb + nt * 8;
                if (c0     > qr0) s[nt][0] = -1e30f;
                if (c0 + 1 > qr0) s[nt][1] = -1e30f;
                if (c0     > qr1) s[nt][2] = -1e30f;
                if (c0 + 1 > qr1) s[nt][3] = -1e30f;
            }
        }

        // ---- online softmax (rows g and g+8 of the strip) ----
        float mx0 = -1e30f, mx1 = -1e30f;
#pragma unroll
        for (int nt = 0; nt < 8; nt++) {
            mx0 = fmaxf(mx0, fmaxf(s[nt][0], s[nt][1]));
            mx1 = fmaxf(mx1, fmaxf(s[nt][2], s[nt][3]));
        }
        mx0 = fmaxf(mx0, __shfl_xor_sync(0xffffffffu, mx0, 1));
        mx0 = fmaxf(mx0, __shfl_xor_sync(0xffffffffu, mx0, 2));
        mx1 = fmaxf(mx1, __shfl_xor_sync(0xffffffffu, mx1, 1));
        mx1 = fmaxf(mx1, __shfl_xor_sync(0xffffffffu, mx1, 2));
        float mn0 = fmaxf(m0, mx0), mn1 = fmaxf(m1, mx1);
        float al0 = __expf(m0 - mn0), al1 = __expf(m1 - mn1);
        m0 = mn0; m1 = mn1;
        float su0 = 0.f, su1 = 0.f;
#pragma unroll
        for (int nt = 0; nt < 8; nt++) {
            float p0 = __expf(s[nt][0] - mn0);
            float p1 = __expf(s[nt][1] - mn0);
            float p2 = __expf(s[nt][2] - mn1);
            float p3 = __expf(s[nt][3] - mn1);
            su0 += p0 + p1; su1 += p2 + p3;
            *reinterpret_cast<float2*>(Pw  + nt * 8 + 2 * tig) =
                make_float2(tf32rn(p0), tf32rn(p1));
            *reinterpret_cast<float2*>(Pw8 + nt * 8 + 2 * tig) =
                make_float2(tf32rn(p2), tf32rn(p3));
        }
        su0 += __shfl_xor_sync(0xffffffffu, su0, 1);
        su0 += __shfl_xor_sync(0xffffffffu, su0, 2);
        su1 += __shfl_xor_sync(0xffffffffu, su1, 1);
        su1 += __shfl_xor_sync(0xffffffffu, su1, 2);
        l0 = l0 * al0 + su0;
        l1 = l1 * al1 + su1;

        // ---- rescale O in regs ----
#pragma unroll
        for (int nt = 0; nt < 16; nt++) {
            o[nt][0] *= al0; o[nt][1] *= al0; o[nt][2] *= al1; o[nt][3] *= al1;
        }
        __syncwarp();

        // ---- O += P V ----
#pragma unroll
        for (int ks = 0; ks < 8; ks++) {
            int kc = ks * 8 + tig;
            unsigned a0 = fbits(Pw[kc]);
            unsigned a1 = fbits(Pw8[kc]);
            unsigned a2 = fbits(Pw[kc + 4]);
            unsigned a3 = fbits(Pw8[kc + 4]);
#pragma unroll
            for (int nt = 0; nt < 16; nt++) {
                unsigned b0 = fbits(Vs[(ks * 8 + tig) * VLD + nt * 8 + g]);
                unsigned b1 = fbits(Vs[(ks * 8 + tig + 4) * VLD + nt * 8 + g]);
                mma8(o[nt], a0, a1, a2, a3, b0, b1);
            }
        }
    }

    // ---- normalize + write ----
    float inv0 = 1.f / l0, inv1 = 1.f / l1;
    float* crow  = ctx + (size_t)(t0 + warp * 16 + g) * HDIM + qcol;
    float* crow8 = crow + (size_t)8 * HDIM;
#pragma unroll
    for (int nt = 0; nt < 16; nt++) {
        *reinterpret_cast<float2*>(crow  + nt * 8 + 2 * tig) =
            make_float2(o[nt][0] * inv0, o[nt][1] * inv0);
        *reinterpret_cast<float2*>(crow8 + nt * 8 + 2 * tig) =
            make_float2(o[nt][2] * inv1, o[nt][3] * inv1);
    }
}

// ---------------- launch ----------------
extern "C" void kernel_launch(void* const* d_in, const int* in_sizes, int n_in,
                              void* d_out, int out_size)
{
    const int*   positions    = (const int*)d_in[0];
    const float* hidden       = (const float*)d_in[1];
    const int*   slot_mapping = (const int*)d_in[4];
    const float* w_qkv        = (const float*)d_in[n_in - 3];
    const float* b_qkv        = (const float*)d_in[n_in - 2];
    const float* w_o          = (const float*)d_in[n_in - 1];

    float* out   = (float*)d_out;
    float* cache = out + OUT_ELEMS;

    float* qkv = nullptr;
    float* ctx = nullptr;
    cudaGetSymbolAddress((void**)&qkv, g_qkv);
    cudaGetSymbolAddress((void**)&ctx, g_ctx);

    cudaFuncSetAttribute(gemm_tf32_nt, cudaFuncAttributeMaxDynamicSharedMemorySize, GEMM_SMEM_BYTES);
    cudaFuncSetAttribute(attn_kernel,  cudaFuncAttributeMaxDynamicSharedMemorySize, ATTN_SMEM_BYTES);

    // 1. zero cache region (2 * 8192 * 512 floats)
    zero_kernel<<<1024, 256>>>((float4*)cache, (2 * CACHE_HALF) / 4);

    // 2. qkv = hidden @ w_qkv^T
    gemm_tf32_nt<<<dim3(QKV_N / BN, T_TOK / BM), 256, GEMM_SMEM_BYTES>>>(
        hidden, w_qkv, qkv, T_TOK, QKV_N, HDIM);

    // 3. bias + rope + cache scatter
    epi_kernel<<<T_TOK, 64>>>(qkv, b_qkv, positions, slot_mapping, cache);

    // 4. attention -> ctx
    attn_kernel<<<dim3(SEQ / QT, NH, BATCH), 256, ATTN_SMEM_BYTES>>>(qkv, ctx);

    // 5. out = ctx @ w_o^T
    gemm_tf32_nt<<<dim3(HDIM / BN, T_TOK / BM), 256, GEMM_SMEM_BYTES>>>(
        ctx, w_o, out, T_TOK, HDIM, HDIM);
}